// round 4
// baseline (speedup 1.0000x reference)
#include <cuda_runtime.h>
#include <cstdint>

// LIF spike recurrence over the last (time) axis.
//   u = TAU*u*(1-o_prev) + x_t;  o = (u > VTH) ? 1 : 0
// x: [16,128,512,32] fp32 -> 1,048,576 neurons x 32 contiguous timesteps.
//
// Round 4: ballot-packed output. Input still flows through a cp.async
// double-buffered smem transpose (coalesced reads), but spikes are 1-bit:
// each timestep's warp-wide spike pattern is captured with __ballot_sync
// (mask for timestep t parked in lane t), and the coalesced float4 stores
// are reconstructed via __shfl + bit extract. No smem on the output path,
// no WAR barrier before buffer reuse (the final ballot warp-syncs lanes
// past their last smem read), stores overlap next tile's async reads.

#define TAU 0.25f
#define VTH 0.5f

#define THREADS 128
#define WARPS 4
#define F4_PER_WARP 256                    // 32 neurons * 8 float4
#define F4_PER_TILE (WARPS * F4_PER_WARP)  // 1024 float4 = 16 KB
#define FULLM 0xFFFFFFFFu

__device__ __forceinline__ void cp_async16(uint32_t smem_addr, const void* gptr) {
    asm volatile("cp.async.cg.shared.global [%0], [%1], 16;\n"
                 :: "r"(smem_addr), "l"(gptr) : "memory");
}
__device__ __forceinline__ void cp_commit() {
    asm volatile("cp.async.commit_group;\n" ::: "memory");
}
template <int N>
__device__ __forceinline__ void cp_wait() {
    asm volatile("cp.async.wait_group %0;\n" :: "n"(N) : "memory");
}

__global__ __launch_bounds__(THREADS, 6)
void lif_kernel(const float4* __restrict__ x, float4* __restrict__ out,
                int ntiles) {
    __shared__ float4 buf[2][F4_PER_TILE];  // 32 KB

    const int lane = threadIdx.x & 31;
    const int warp = threadIdx.x >> 5;

    auto prefetch = [&](int tile, int b) {
        const size_t gbase = (size_t)tile * F4_PER_TILE + (size_t)warp * F4_PER_WARP;
        uint32_t sbase = (uint32_t)__cvta_generic_to_shared(
            &buf[b][warp * F4_PER_WARP]);
        #pragma unroll
        for (int i = 0; i < 8; i++) {
            int g = i * 32 + lane;
            int n = g >> 3;
            int j = g & 7;
            cp_async16(sbase + (((n << 3) | (j ^ (n & 7))) * 16u),
                       &x[gbase + g]);
        }
        cp_commit();
    };

    int tile = blockIdx.x;
    int b = 0;
    if (tile < ntiles) prefetch(tile, 0);

    for (; tile < ntiles; tile += gridDim.x) {
        const int next = tile + gridDim.x;
        if (next < ntiles) {
            prefetch(next, b ^ 1);
            cp_wait<1>();
        } else {
            cp_wait<0>();
        }
        __syncwarp();   // make lane-issued cp.async data visible warp-wide

        const float4* wtile = &buf[b][warp * F4_PER_WARP];

        // Recurrence: lane owns neuron `lane`. Spike bits captured by ballot;
        // mask for timestep t ends up in lane t's mask register.
        uint32_t mask = 0;
        {
            const int n = lane;
            float u = 0.0f, o = 0.0f;
            #pragma unroll
            for (int j = 0; j < 8; j++) {
                float4 f = wtile[(n << 3) | (j ^ (n & 7))];

                #pragma unroll
                for (int k = 0; k < 4; k++) {
                    float xv = (k == 0) ? f.x : (k == 1) ? f.y
                             : (k == 2) ? f.z : f.w;
                    u = TAU * u * (1.0f - o) + xv;
                    bool s = (u > VTH);
                    o = s ? 1.0f : 0.0f;
                    uint32_t m = __ballot_sync(FULLM, s);
                    const int t = j * 4 + k;
                    mask = (lane == t) ? m : mask;
                }
            }
        }
        // (final ballot has synchronized all lanes past their smem reads:
        //  buffer b is safe to recycle next iteration without a barrier)

        // Coalesced float4 stores reconstructed from the 32 masks.
        {
            const size_t gbase = (size_t)tile * F4_PER_TILE + (size_t)warp * F4_PER_WARP;
            #pragma unroll
            for (int i = 0; i < 8; i++) {
                int g = i * 32 + lane;
                int n = g >> 3;
                int t0 = (g & 7) * 4;
                float4 v;
                v.x = (float)((__shfl_sync(FULLM, mask, t0 + 0) >> n) & 1u);
                v.y = (float)((__shfl_sync(FULLM, mask, t0 + 1) >> n) & 1u);
                v.z = (float)((__shfl_sync(FULLM, mask, t0 + 2) >> n) & 1u);
                v.w = (float)((__shfl_sync(FULLM, mask, t0 + 3) >> n) & 1u);
                __stcs(&out[gbase + g], v);
            }
        }

        b ^= 1;
    }
}

extern "C" void kernel_launch(void* const* d_in, const int* in_sizes, int n_in,
                              void* d_out, int out_size) {
    const float4* x = (const float4*)d_in[0];
    float4* o = (float4*)d_out;

    long long n_floats = in_sizes[0];                  // 33,554,432
    long long neurons = n_floats / 32;                 // 1,048,576
    int ntiles = (int)(neurons / (F4_PER_TILE / 8));   // 8192 tiles of 128 neurons

    int blocks = 6 * 148;                              // one resident wave
    if (blocks > ntiles) blocks = ntiles;

    lif_kernel<<<blocks, THREADS>>>(x, o, ntiles);
}